// round 2
// baseline (speedup 1.0000x reference)
#include <cuda_runtime.h>
#include <math.h>

// Problem constants
#define Bb   64
#define Cc   64
#define Ll   8192
#define Ff   4097          // rfft bins
#define NFFT 4096          // complex FFT size (L/2)
#define HID  128
#define NT   33            // f-tiles of 128 covering 4097

// ---------------- scratch (device globals; no allocations allowed) ----------
__device__ float g_fxre[Bb * Cc * Ff];          // 67 MB  rfft real (ortho)
__device__ float g_fxim[Bb * Cc * Ff];          // 67 MB  rfft imag (ortho)
__device__ float g_part[2 * Bb * HID * NT];     // per-tile partial SELU sums
__device__ float g_edge[2 * Bb * HID * 2];      // y[h,0], y[h,F-1]
__device__ float g_C[2 * Bb * 3];               // softmax coefficients C_R, C_I

// ---------------- 4096-pt radix-2 Stockham FFT in shared memory -------------
// sign = -1: forward DFT (e^{-i...}), sign = +1: unscaled inverse (e^{+i...}).
// 12 stages, ping-pong buffers; result lands back in (sr, si).
__device__ __forceinline__ void fft4096(float* sr, float* si, float* dr, float* di,
                                        int tid, float sign) {
#pragma unroll 1
    for (int t = 0; t < 12; t++) {
        int   s      = 1 << t;
        float theta0 = sign * (6.283185307179586f / (float)(NFFT >> t));
        __syncthreads();
#pragma unroll
        for (int i = 0; i < 8; i++) {
            int u = tid + (i << 8);
            int q = u & (s - 1);
            int p = u >> t;
            float cw, sw;
            __sincosf(theta0 * (float)p, &sw, &cw);
            int   i0  = q + s * p;
            int   i1  = i0 + 2048;          // s * (n/2) == 2048 at every stage
            float x0r = sr[i0], x0i = si[i0];
            float x1r = sr[i1], x1i = si[i1];
            int   o0  = q + 2 * s * p;
            dr[o0] = x0r + x1r;
            di[o0] = x0i + x1i;
            float tr = x0r - x1r, ti = x0i - x1i;
            dr[o0 + s] = tr * cw - ti * sw;
            di[o0 + s] = tr * sw + ti * cw;
        }
        float* tp;
        tp = sr; sr = dr; dr = tp;
        tp = si; si = di; di = tp;
    }
    __syncthreads();
}

// ---------------- K1: forward rfft (ortho) -----------------------------------
__global__ void __launch_bounds__(256) k_fwd(const float* __restrict__ x) {
    extern __shared__ float sm[];
    float* ar = sm;
    float* ai = sm + 4096;
    float* br = sm + 8192;
    float* bi = sm + 12288;
    int row = blockIdx.x;                    // row = b*64 + c
    int tid = threadIdx.x;

    const float2* xin = (const float2*)(x + (size_t)row * Ll);
#pragma unroll
    for (int i = 0; i < 16; i++) {
        int    m = tid + (i << 8);
        float2 v = xin[m];
        ar[m] = v.x;                         // even samples
        ai[m] = v.y;                         // odd samples
    }
    fft4096(ar, ai, br, bi, tid, -1.0f);

    // Hermitian unpack: X[k] = E[k] + W^k O[k], W^k = e^{-i pi k / 4096}
    const float sc   = 0.011048543456039804f;   // 1/sqrt(8192)  (ortho)
    float* outre = g_fxre + (size_t)row * Ff;
    float* outim = g_fxim + (size_t)row * Ff;
    for (int k = tid; k < Ff; k += 256) {
        int   ka  = k & 4095;
        int   kb  = (4096 - k) & 4095;
        float zkr = ar[ka], zki = ai[ka];
        float zmr = ar[kb], zmi = ai[kb];
        float Er = 0.5f * (zkr + zmr), Ei = 0.5f * (zki - zmi);
        float Or = 0.5f * (zki + zmi), Oi = 0.5f * (zmr - zkr);
        float ang = (float)k * (3.14159265358979324f / 4096.0f);
        float cw, sw;
        __sincosf(ang, &sw, &cw);            // w = (cw, -sw)
        float Xr = Er + cw * Or + sw * Oi;
        float Xi = Ei + cw * Oi - sw * Or;
        outre[k] = Xr * sc;
        outim[k] = Xi * sc;
    }
}

// ---------------- K2a: conv1 (64->128, K=3) + SELU + partial f-sum ----------
// grid (33 tiles, 64 batch, 2 paths), 256 threads, 8h x 8f register tile.
__global__ void __launch_bounds__(256) k_conv(const float* __restrict__ w1R,
                                              const float* __restrict__ b1R,
                                              const float* __restrict__ w1I,
                                              const float* __restrict__ b1I) {
    __shared__ float sh_x[16][132];          // [c-chunk][f0-1 .. f0+128]
    __shared__ float sh_w[16][384];          // [c-chunk][h*3 + k]

    int tile = blockIdx.x;
    int b    = blockIdx.y;
    int path = blockIdx.z;
    const float* in = (path == 0) ? g_fxre : g_fxim;
    const float* w1 = (path == 0) ? w1R : w1I;
    const float* b1 = (path == 0) ? b1R : b1I;

    int tid = threadIdx.x;
    int tx  = tid & 15;                      // f group
    int ty  = tid >> 4;                      // h group
    int f0  = tile * 128;

    float acc[8][8];
#pragma unroll
    for (int i = 0; i < 8; i++)
#pragma unroll
        for (int j = 0; j < 8; j++) acc[i][j] = 0.f;

    for (int c0 = 0; c0 < 64; c0 += 16) {
        __syncthreads();
        for (int idx = tid; idx < 16 * 130; idx += 256) {
            int cc = idx / 130;
            int j  = idx - cc * 130;
            int f  = f0 - 1 + j;
            float v = 0.f;
            if (f >= 0 && f < Ff)
                v = in[((size_t)(b * 64 + c0 + cc)) * Ff + f];
            sh_x[cc][j] = v;
        }
        for (int idx = tid; idx < 16 * 384; idx += 256) {
            int cc = idx / 384;
            int r  = idx - cc * 384;
            int h  = r / 3;
            int k  = r - h * 3;
            sh_w[cc][r] = w1[((size_t)h * 64 + c0 + cc) * 3 + k];
        }
        __syncthreads();
#pragma unroll 1
        for (int cc = 0; cc < 16; cc++) {
            float xv[10];
#pragma unroll
            for (int j = 0; j < 10; j++) xv[j] = sh_x[cc][tx * 8 + j];
#pragma unroll
            for (int hh = 0; hh < 8; hh++) {
                int   hb = (ty * 8 + hh) * 3;
                float w0 = sh_w[cc][hb + 0];
                float wa = sh_w[cc][hb + 1];
                float wb = sh_w[cc][hb + 2];
#pragma unroll
                for (int ff = 0; ff < 8; ff++) {
                    float a = acc[hh][ff];
                    a = fmaf(w0, xv[ff], a);
                    a = fmaf(wa, xv[ff + 1], a);
                    a = fmaf(wb, xv[ff + 2], a);
                    acc[hh][ff] = a;
                }
            }
        }
    }

    // bias + SELU + partial reduction over this tile's f range
    const float SC = 1.0507009873554805f, AL = 1.6732632423543772f;
#pragma unroll
    for (int hh = 0; hh < 8; hh++) {
        int   h    = ty * 8 + hh;
        float bias = b1[h];
        float s    = 0.f;
#pragma unroll
        for (int ff = 0; ff < 8; ff++) {
            int   f = f0 + tx * 8 + ff;
            float v = acc[hh][ff] + bias;
            float y = SC * ((v > 0.f) ? v : AL * expm1f(v));
            if (f < Ff) {
                s += y;
                size_t eb = (((size_t)path * 64 + b) * 128 + h) * 2;
                if (f == 0)      g_edge[eb + 0] = y;
                if (f == Ff - 1) g_edge[eb + 1] = y;
            }
        }
#pragma unroll
        for (int off = 8; off >= 1; off >>= 1)
            s += __shfl_xor_sync(0xffffffffu, s, off, 16);
        if (tx == 0)
            g_part[(((size_t)path * 64 + b) * 128 + h) * NT + tile] = s;
    }
}

// ---------------- K2b: pooled conv2 + softmax --------------------------------
// conv2 + mean-pool collapses to: (1/F) * sum_h [ w2[n,h,0](S-yL) + w2[n,h,1]S
//                                               + w2[n,h,2](S-y0) ] + b2[n]
__global__ void __launch_bounds__(128) k_pool(const float* __restrict__ w2R,
                                              const float* __restrict__ b2R,
                                              const float* __restrict__ w2I,
                                              const float* __restrict__ b2I) {
    int bx   = blockIdx.x;
    int path = bx >> 6;
    int b    = bx & 63;
    const float* w2 = path ? w2I : w2R;
    const float* b2 = path ? b2I : b2R;
    int h = threadIdx.x;

    size_t base = ((size_t)path * 64 + b) * 128 + h;
    float  S    = 0.f;
#pragma unroll
    for (int t = 0; t < NT; t++) S += g_part[base * NT + t];
    float y0 = g_edge[base * 2 + 0];
    float yl = g_edge[base * 2 + 1];

    __shared__ float red[3][128];
#pragma unroll
    for (int n = 0; n < 3; n++) {
        const float* wp = w2 + ((size_t)n * 128 + h) * 3;
        red[n][h] = wp[0] * (S - yl) + wp[1] * S + wp[2] * (S - y0);
    }
    __syncthreads();
    for (int off = 64; off >= 1; off >>= 1) {
        if (h < off) {
#pragma unroll
            for (int n = 0; n < 3; n++) red[n][h] += red[n][h + off];
        }
        __syncthreads();
    }
    if (h == 0) {
        float z0 = red[0][0] / (float)Ff + b2[0];
        float z1 = red[1][0] / (float)Ff + b2[1];
        float z2 = red[2][0] / (float)Ff + b2[2];
        float m  = fmaxf(z0, fmaxf(z1, z2));
        float e0 = expf(z0 - m), e1 = expf(z1 - m), e2 = expf(z2 - m);
        float inv = 1.f / (e0 + e1 + e2);
        size_t cb = ((size_t)path * 64 + b) * 3;
        g_C[cb + 0] = e0 * inv;
        g_C[cb + 1] = e1 * inv;
        g_C[cb + 2] = e2 * inv;
    }
}

// ---------------- K3: Kf, spectral multiply, irfft (ortho) -------------------
__global__ void __launch_bounds__(256) k_inv(const float* __restrict__ param,
                                             float* __restrict__ out) {
    extern __shared__ float sm[];
    __shared__ float extra[2];               // Y[4096] (Nyquist)
    float* ar = sm;
    float* ai = sm + 4096;
    float* br = sm + 8192;
    float* bi = sm + 12288;

    int row = blockIdx.x;
    int b   = row >> 6;
    int c   = row & 63;
    int tid = threadIdx.x;

    float cr0 = g_C[((size_t)0 * 64 + b) * 3 + 0];
    float cr1 = g_C[((size_t)0 * 64 + b) * 3 + 1];
    float cr2 = g_C[((size_t)0 * 64 + b) * 3 + 2];
    float ci0 = g_C[((size_t)1 * 64 + b) * 3 + 0];
    float ci1 = g_C[((size_t)1 * 64 + b) * 3 + 1];
    float ci2 = g_C[((size_t)1 * 64 + b) * 3 + 2];

    const float* fre = g_fxre + (size_t)row * Ff;
    const float* fim = g_fxim + (size_t)row * Ff;

    for (int f = tid; f < Ff; f += 256) {
        float2 w0 = *(const float2*)(param + (((size_t)0 * 64 + c) * Ff + f) * 2);
        float2 w1 = *(const float2*)(param + (((size_t)1 * 64 + c) * Ff + f) * 2);
        float2 w2 = *(const float2*)(param + (((size_t)2 * 64 + c) * Ff + f) * 2);
        float KfR = cr0 * w0.x + cr1 * w1.x + cr2 * w2.x;
        float KfI = ci0 * w0.y + ci1 * w1.y + ci2 * w2.y;
        float fr = fre[f], fi = fim[f];
        float Yr = fr * KfR - fi * KfI;
        float Yi = fr * KfI + fi * KfR;
        if (f == 0) Yi = 0.f;                // C2R discards imag of DC
        if (f < 4096) { ar[f] = Yr; ai[f] = Yi; }
        else          { extra[0] = Yr; extra[1] = 0.f; }  // ... and of Nyquist
    }
    __syncthreads();

    // Inverse packing: Z[k] = E[k] + i O[k]
    for (int k = tid; k < 4096; k += 256) {
        float Xkr = ar[k], Xki = ai[k];
        float Xmr, Xmi;
        if (k == 0) { Xmr = extra[0]; Xmi = extra[1]; }
        else        { Xmr = ar[4096 - k]; Xmi = ai[4096 - k]; }
        float Er = 0.5f * (Xkr + Xmr), Ei = 0.5f * (Xki - Xmi);
        float Dr = 0.5f * (Xkr - Xmr), Di = 0.5f * (Xki + Xmi);
        float ang = (float)k * (3.14159265358979324f / 4096.0f);
        float cw, sw;
        __sincosf(ang, &sw, &cw);            // W^{-k} = e^{+i ang}
        float Or = Dr * cw - Di * sw;
        float Oi = Dr * sw + Di * cw;
        br[k] = Er - Oi;
        bi[k] = Ei + Or;
    }
    fft4096(br, bi, ar, ai, tid, +1.0f);     // unscaled inverse; result in br/bi

    const float sc = 0.022097086912079608f;  // sqrt(8192) / 4096  (ortho)
    float2* o = (float2*)(out + (size_t)row * Ll);
    for (int m = tid; m < 4096; m += 256)
        o[m] = make_float2(br[m] * sc, bi[m] * sc);
}

// ---------------- launch -----------------------------------------------------
extern "C" void kernel_launch(void* const* d_in, const int* in_sizes, int n_in,
                              void* d_out, int out_size) {
    const float* x   = (const float*)d_in[0];
    const float* par = (const float*)d_in[1];
    const float* wR1 = (const float*)d_in[2];
    const float* bR1 = (const float*)d_in[3];
    const float* wR2 = (const float*)d_in[4];
    const float* bR2 = (const float*)d_in[5];
    const float* wI1 = (const float*)d_in[6];
    const float* bI1 = (const float*)d_in[7];
    const float* wI2 = (const float*)d_in[8];
    const float* bI2 = (const float*)d_in[9];
    float* out = (float*)d_out;

    cudaFuncSetAttribute(k_fwd, cudaFuncAttributeMaxDynamicSharedMemorySize, 65536);
    cudaFuncSetAttribute(k_inv, cudaFuncAttributeMaxDynamicSharedMemorySize, 65536);

    k_fwd<<<Bb * Cc, 256, 65536>>>(x);
    dim3 g2(NT, Bb, 2);
    k_conv<<<g2, 256>>>(wR1, bR1, wI1, bI1);
    k_pool<<<2 * Bb, 128>>>(wR2, bR2, wI2, bI2);
    k_inv<<<Bb * Cc, 256, 65536>>>(par, out);
}